// round 2
// baseline (speedup 1.0000x reference)
#include <cuda_runtime.h>
#include <cuda_bf16.h>
#include <cstdint>

#define N_NODES 50000
#define NNZ     1600000
#define F       128        // D*B
#define M_MATS  7
#define U_DIM   64
#define NF      (N_NODES * F)
#define KSPLIT  32
#define KCH     1568       // 31*1568=48608; last chunk 1392 (=87*16)

// ---------------- device scratch (static, no allocation) ----------------
__device__ float g_x[(size_t)M_MATS * NF];            // xs[0..6], each (N, F)
__device__ int   g_colL[NNZ];
__device__ float g_valL[NNZ];
__device__ int   g_colR[NNZ];
__device__ float g_valR[NNZ];
__device__ int   g_rowptrL[N_NODES + 1];
__device__ int   g_rowptrR[N_NODES + 1];
__device__ int   g_cnt[N_NODES];
__device__ float g_part[(size_t)KSPLIT * M_MATS * F * 128];  // [ks][m][f][0:64]=u-lin, [64:128]=c-lin

// ---------------- CSR build ----------------
__global__ void zero_cnt() {
    int i = blockIdx.x * blockDim.x + threadIdx.x;
    if (i < N_NODES) g_cnt[i] = 0;
}

__global__ void hist_rows(const int* __restrict__ rows) {
    int e = blockIdx.x * blockDim.x + threadIdx.x;
    if (e < NNZ) atomicAdd(&g_cnt[rows[e]], 1);
}

// single-block exclusive scan of g_cnt -> rowptr, rowptr[N]=NNZ
__global__ void scan_cnt(int sel /*0=L,1=R*/) {
    int* rowptr = sel ? g_rowptrR : g_rowptrL;
    __shared__ int warp_sums[32];
    __shared__ int s_carry;
    int tid = threadIdx.x;  // 1024 threads
    if (tid == 0) s_carry = 0;
    __syncthreads();
    for (int base = 0; base < N_NODES; base += 1024) {
        int i = base + tid;
        int v = (i < N_NODES) ? g_cnt[i] : 0;
        int x = v;
        #pragma unroll
        for (int o = 1; o < 32; o <<= 1) {
            int y = __shfl_up_sync(0xffffffffu, x, o);
            if ((tid & 31) >= o) x += y;
        }
        if ((tid & 31) == 31) warp_sums[tid >> 5] = x;
        __syncthreads();
        if (tid < 32) {
            int w = warp_sums[tid];
            #pragma unroll
            for (int o = 1; o < 32; o <<= 1) {
                int y = __shfl_up_sync(0xffffffffu, w, o);
                if (tid >= o) w += y;
            }
            warp_sums[tid] = w;
        }
        __syncthreads();
        int warp_off = (tid >= 32) ? warp_sums[(tid >> 5) - 1] : 0;
        int incl = x + warp_off;
        int carry = s_carry;
        if (i < N_NODES) rowptr[i] = carry + incl - v;
        __syncthreads();
        if (tid == 1023) s_carry = carry + incl;
        __syncthreads();
    }
    if (tid == 0) rowptr[N_NODES] = NNZ;
}

__global__ void scatter_edges(const int* __restrict__ rows, const int* __restrict__ cols,
                              const float* __restrict__ vals, int sel) {
    int e = blockIdx.x * blockDim.x + threadIdx.x;
    if (e >= NNZ) return;
    const int* rowptr = sel ? g_rowptrR : g_rowptrL;
    int* colout = sel ? g_colR : g_colL;
    float* valout = sel ? g_valR : g_valL;
    int r = rows[e];
    int p = rowptr[r] + atomicAdd(&g_cnt[r], 1);
    colout[p] = cols[e];
    valout[p] = vals[e];
}

// ---------------- x0 build: x0[n, d*64+b] = inputs[b,n,d] ----------------
__global__ void build_x0(const float* __restrict__ inputs) {
    int idx = blockIdx.x * blockDim.x + threadIdx.x;  // over N*64
    if (idx >= N_NODES * 64) return;
    int b = idx & 63;
    int n = idx >> 6;
    float2 v = __ldg((const float2*)inputs + (size_t)b * N_NODES + n);
    g_x[n * F + b] = v.x;
    g_x[n * F + 64 + b] = v.y;
}

// ---------------- SpMM: out = S @ x with fused epilogues ----------------
// 1 row per 128-thread block; edges staged through shared memory.
// mode 0: out = acc
// mode 1: out = 2*acc - sub
// mode 2: out = 2*acc - sub;  out2 = acc
__global__ void __launch_bounds__(128) spmm(int mat /*0=L,1=R*/, int xi, int oi, int si, int o2i, int mode) {
    __shared__ int   s_col[128];
    __shared__ float s_val[128];
    int row = blockIdx.x;
    int f = threadIdx.x;  // 0..127
    const int* rowptr = mat ? g_rowptrR : g_rowptrL;
    const int* colx = mat ? g_colR : g_colL;
    const float* valx = mat ? g_valR : g_valL;
    const float* x = g_x + (size_t)xi * NF;
    int e0 = __ldg(rowptr + row);
    int e1 = __ldg(rowptr + row + 1);
    float acc = 0.f;
    for (int base = e0; base < e1; base += 128) {
        int n = e1 - base;
        if (n > 128) n = 128;
        if (f < n) {
            s_col[f] = __ldg(colx + base + f) * F;
            s_val[f] = __ldg(valx + base + f);
        }
        __syncthreads();
        int k = 0;
        for (; k + 1 < n; k += 2) {
            int   c0 = s_col[k],     c1 = s_col[k + 1];
            float v0 = s_val[k],     v1 = s_val[k + 1];
            acc += v0 * __ldg(x + c0 + f);
            acc += v1 * __ldg(x + c1 + f);
        }
        if (k < n) acc += s_val[k] * __ldg(x + s_col[k] + f);
        __syncthreads();
    }
    int o = row * F + f;
    if (mode == 0) {
        g_x[(size_t)oi * NF + o] = acc;
    } else if (mode == 1) {
        g_x[(size_t)oi * NF + o] = 2.f * acc - g_x[(size_t)si * NF + o];
    } else {
        g_x[(size_t)oi * NF + o] = 2.f * acc - g_x[(size_t)si * NF + o];
        g_x[(size_t)o2i * NF + o] = acc;
    }
}

// ---------------- GEMM split-K: partial[ks][m][f][col] ----------------
// which=0: cols 0:64 of partial = xs[m]^T @ w_ru[:,64:128] (u-gate linear)
// which=1: cols 64:128 of partial = xs[m]^T @ w_c (c linear)
__global__ void __launch_bounds__(256) gemm_part(const float* __restrict__ w_ru,
                                                 const float* __restrict__ w_c) {
    int ks = blockIdx.x;
    int m = blockIdx.y;
    int t = blockIdx.z;
    int ftile = t >> 1, which = t & 1;
    int f0 = ftile * 64;
    const float* A = g_x + (size_t)m * NF;  // A[n*128 + f]
    const float* Bw;
    int ldw;
    if (which == 0) { Bw = w_ru + 64; ldw = 128; }
    else            { Bw = w_c;       ldw = 64; }
    int n0 = ks * KCH;
    int n1 = n0 + KCH;
    if (n1 > N_NODES) n1 = N_NODES;

    __shared__ float As[16][64];
    __shared__ float Bs[16][64];
    int tid = threadIdx.x;
    int ty = tid >> 4, tx = tid & 15;
    int lk = tid >> 4;           // loader row 0..15
    int lf4 = (tid & 15) * 4;    // loader col group

    float acc[4][4];
    #pragma unroll
    for (int i = 0; i < 4; i++)
        #pragma unroll
        for (int j = 0; j < 4; j++) acc[i][j] = 0.f;

    for (int n = n0; n < n1; n += 16) {
        float4 av = *(const float4*)(A + (size_t)(n + lk) * F + f0 + lf4);
        float4 bv = *(const float4*)(Bw + (size_t)(n + lk) * ldw + lf4);
        *(float4*)&As[lk][lf4] = av;
        *(float4*)&Bs[lk][lf4] = bv;
        __syncthreads();
        #pragma unroll
        for (int k = 0; k < 16; k++) {
            float4 a = *(const float4*)&As[k][ty * 4];
            float4 b = *(const float4*)&Bs[k][tx * 4];
            acc[0][0] += a.x * b.x; acc[0][1] += a.x * b.y; acc[0][2] += a.x * b.z; acc[0][3] += a.x * b.w;
            acc[1][0] += a.y * b.x; acc[1][1] += a.y * b.y; acc[1][2] += a.y * b.z; acc[1][3] += a.y * b.w;
            acc[2][0] += a.z * b.x; acc[2][1] += a.z * b.y; acc[2][2] += a.z * b.z; acc[2][3] += a.z * b.w;
            acc[3][0] += a.w * b.x; acc[3][1] += a.w * b.y; acc[3][2] += a.w * b.z; acc[3][3] += a.w * b.w;
        }
        __syncthreads();
    }

    float* P = g_part + ((size_t)ks * M_MATS + m) * F * 128;
    #pragma unroll
    for (int i = 0; i < 4; i++) {
        #pragma unroll
        for (int j = 0; j < 4; j++) {
            P[(f0 + ty * 4 + i) * 128 + which * 64 + tx * 4 + j] = acc[i][j];
        }
    }
}

// ---------------- reduce partials + bias + GRU epilogue ----------------
__global__ void finish(const float* __restrict__ hx, const float* __restrict__ b_ru,
                       const float* __restrict__ b_c, float* __restrict__ out) {
    int idx = blockIdx.x * blockDim.x + threadIdx.x;  // over 7*128*64
    if (idx >= M_MATS * F * U_DIM) return;
    int j = idx & 63;
    int f = (idx >> 6) & 127;
    int m = idx >> 13;
    float su = __ldg(b_ru + 64 + j);
    float sc = __ldg(b_c + j);
    const float* P = g_part + (size_t)m * F * 128 + f * 128;
    #pragma unroll 4
    for (int ks = 0; ks < KSPLIT; ks++) {
        const float* Pk = P + (size_t)ks * M_MATS * F * 128;
        su += Pk[j];
        sc += Pk[64 + j];
    }
    float u = 1.f / (1.f + expf(-su));
    int r = f * M_MATS + m;
    float h = __ldg(hx + r * U_DIM + j);
    out[r * U_DIM + j] = u * h + (1.f - u) * tanhf(sc);
}

// ---------------- launcher ----------------
extern "C" void kernel_launch(void* const* d_in, const int* in_sizes, int n_in,
                              void* d_out, int out_size) {
    const float* inputs   = (const float*)d_in[0];
    const float* hx       = (const float*)d_in[1];
    const float* w_ru     = (const float*)d_in[2];
    const float* b_ru     = (const float*)d_in[3];
    const float* w_c      = (const float*)d_in[4];
    const float* b_c      = (const float*)d_in[5];
    const float* lap_vals = (const float*)d_in[6];
    const float* rw_vals  = (const float*)d_in[7];
    const int*   lap_rows = (const int*)d_in[8];
    const int*   lap_cols = (const int*)d_in[9];
    const int*   rw_rows  = (const int*)d_in[10];
    const int*   rw_cols  = (const int*)d_in[11];
    float* out = (float*)d_out;

    const int TB = 256;
    const int gN = (N_NODES + TB - 1) / TB;
    const int gE = (NNZ + TB - 1) / TB;

    // Build CSR for L (scaled laplacian)
    zero_cnt<<<gN, TB>>>();
    hist_rows<<<gE, TB>>>(lap_rows);
    scan_cnt<<<1, 1024>>>(0);
    zero_cnt<<<gN, TB>>>();
    scatter_edges<<<gE, TB>>>(lap_rows, lap_cols, lap_vals, 0);

    // Build CSR for R (random-walk transpose)
    zero_cnt<<<gN, TB>>>();
    hist_rows<<<gE, TB>>>(rw_rows);
    scan_cnt<<<1, 1024>>>(1);
    zero_cnt<<<gN, TB>>>();
    scatter_edges<<<gE, TB>>>(rw_rows, rw_cols, rw_vals, 1);

    // x0
    build_x0<<<(N_NODES * 64 + TB - 1) / TB, TB>>>(inputs);

    // SpMM chain:
    // xs1 = L x0; xs2 = 2 L xs1 - x0; xs3 = R xs1; t = R xs3 (xs5 = t, xs4 = 2t - xs1); xs6 = 2 R xs5 - xs3
    spmm<<<N_NODES, 128>>>(0, 0, 1, 0, 0, 0);   // xs1 = L @ x0
    spmm<<<N_NODES, 128>>>(0, 1, 2, 0, 0, 1);   // xs2 = 2*(L @ xs1) - x0
    spmm<<<N_NODES, 128>>>(1, 1, 3, 0, 0, 0);   // xs3 = R @ xs1
    spmm<<<N_NODES, 128>>>(1, 3, 4, 1, 5, 2);   // t = R @ xs3; xs4 = 2t - xs1; xs5 = t
    spmm<<<N_NODES, 128>>>(1, 5, 6, 3, 0, 1);   // xs6 = 2*(R @ xs5) - xs3

    // GEMM partials + fused epilogue
    dim3 gg(KSPLIT, M_MATS, 4);
    gemm_part<<<gg, 256>>>(w_ru, w_c);
    finish<<<(M_MATS * F * U_DIM + TB - 1) / TB, TB>>>(hx, b_ru, b_c, out);
}

// round 4
// speedup vs baseline: 2.1168x; 2.1168x over previous
#include <cuda_runtime.h>
#include <cuda_fp16.h>
#include <cstdint>

#define N_NODES 50000
#define NNZ     1600000
#define F       128        // D*B
#define M_MATS  7
#define U_DIM   64
#define KSPLIT  21
#define KCH     2400       // 21*2400 = 50400 >= 50000, padded with zeros
#define GSTEPS  (KCH / 32) // 75

typedef unsigned int u32;

// ---------------- device scratch (static, no allocation) ----------------
__device__ __half g_xh[(size_t)M_MATS * N_NODES * F];   // xs[0..6] in fp16, (N, F) each
__device__ __half g_wh[(size_t)N_NODES * F];            // [n][j]: j<64 -> w_ru[:,64+j], j>=64 -> w_c[:,j-64]
__device__ int2   g_csr[2][NNZ];                        // {col, val_bits}
__device__ int    g_rowptr[2][N_NODES + 1];
__device__ int    g_cnt[2][N_NODES];
__device__ float  g_part[(size_t)KSPLIT * M_MATS * F * 128];

// ---------------- CSR build ----------------
__global__ void zero2() {
    int i = blockIdx.x * blockDim.x + threadIdx.x;
    if (i < 2 * N_NODES) ((int*)g_cnt)[i] = 0;
}

__global__ void hist2(const int* __restrict__ lr, const int* __restrict__ rr) {
    int e = blockIdx.x * blockDim.x + threadIdx.x;
    if (e >= NNZ) return;
    int sel = blockIdx.y;
    const int* rows = sel ? rr : lr;
    atomicAdd(&g_cnt[sel][rows[e]], 1);
}

// one block per sel; exclusive scan of g_cnt[sel] -> g_rowptr[sel]
__global__ void scan2() {
    int sel = blockIdx.x;
    int* rowptr = g_rowptr[sel];
    const int* cnt = g_cnt[sel];
    __shared__ int warp_sums[32];
    __shared__ int s_carry;
    int tid = threadIdx.x;  // 1024 threads
    if (tid == 0) s_carry = 0;
    __syncthreads();
    for (int base = 0; base < N_NODES; base += 1024) {
        int i = base + tid;
        int v = (i < N_NODES) ? cnt[i] : 0;
        int x = v;
        #pragma unroll
        for (int o = 1; o < 32; o <<= 1) {
            int y = __shfl_up_sync(0xffffffffu, x, o);
            if ((tid & 31) >= o) x += y;
        }
        if ((tid & 31) == 31) warp_sums[tid >> 5] = x;
        __syncthreads();
        if (tid < 32) {
            int w = warp_sums[tid];
            #pragma unroll
            for (int o = 1; o < 32; o <<= 1) {
                int y = __shfl_up_sync(0xffffffffu, w, o);
                if (tid >= o) w += y;
            }
            warp_sums[tid] = w;
        }
        __syncthreads();
        int warp_off = (tid >= 32) ? warp_sums[(tid >> 5) - 1] : 0;
        int incl = x + warp_off;
        int carry = s_carry;
        if (i < N_NODES) rowptr[i] = carry + incl - v;
        __syncthreads();
        if (tid == 1023) s_carry = carry + incl;
        __syncthreads();
    }
    if (tid == 0) rowptr[N_NODES] = NNZ;
}

__global__ void scatter2(const int* __restrict__ lr, const int* __restrict__ lc, const float* __restrict__ lv,
                         const int* __restrict__ rr, const int* __restrict__ rc, const float* __restrict__ rv) {
    int e = blockIdx.x * blockDim.x + threadIdx.x;
    if (e >= NNZ) return;
    int sel = blockIdx.y;
    const int* rows = sel ? rr : lr;
    const int* cols = sel ? rc : lc;
    const float* vals = sel ? rv : lv;
    int r = rows[e];
    int p = g_rowptr[sel][r] + atomicAdd(&g_cnt[sel][r], 1);
    g_csr[sel][p] = make_int2(cols[e], __float_as_int(vals[e]));
}

// ---------------- x0 build: x0[n, d*64+b] = inputs[b,n,d] ----------------
__global__ void build_x0(const float* __restrict__ inputs) {
    int idx = blockIdx.x * blockDim.x + threadIdx.x;  // over N*64
    if (idx >= N_NODES * 64) return;
    int b = idx & 63;
    int n = idx >> 6;
    float2 v = __ldg((const float2*)inputs + (size_t)b * N_NODES + n);
    g_xh[(size_t)n * F + b] = __float2half_rn(v.x);
    g_xh[(size_t)n * F + 64 + b] = __float2half_rn(v.y);
}

// ---------------- merged fp16 weight prep ----------------
__global__ void wprep(const float* __restrict__ w_ru, const float* __restrict__ w_c) {
    int idx = blockIdx.x * blockDim.x + threadIdx.x;  // over N*128
    if (idx >= N_NODES * F) return;
    int n = idx >> 7, j = idx & 127;
    float v = (j < 64) ? __ldg(w_ru + (size_t)n * 128 + 64 + j)
                       : __ldg(w_c + (size_t)n * 64 + (j - 64));
    g_wh[idx] = __float2half_rn(v);
}

// ---------------- SpMM: out = S @ x (fp16 storage, fp32 accumulate) ----------------
// 1 row per 64-thread block; each thread owns 2 f-columns (half2).
// mode 0: out = acc ; mode 1: out = 2*acc - sub ; mode 2: mode1 + out2 = acc
__global__ void __launch_bounds__(64) spmm_h(int mat, int xi, int oi, int si, int o2i, int mode) {
    __shared__ int   s_col[64];
    __shared__ float s_val[64];
    int row = blockIdx.x;
    int t = threadIdx.x;  // 0..63
    const __half2* x = (const __half2*)(g_xh + (size_t)xi * N_NODES * F);
    int e0 = __ldg(&g_rowptr[mat][row]);
    int e1 = __ldg(&g_rowptr[mat][row + 1]);
    float2 acc = make_float2(0.f, 0.f);
    for (int base = e0; base < e1; base += 64) {
        int n = e1 - base;
        if (n > 64) n = 64;
        if (t < n) {
            int2 cv = __ldg(&g_csr[mat][base + t]);
            s_col[t] = cv.x << 6;  // half2 row offset
            s_val[t] = __int_as_float(cv.y);
        }
        __syncthreads();
        int k = 0;
        for (; k + 1 < n; k += 2) {
            int   c0 = s_col[k],   c1 = s_col[k + 1];
            float v0 = s_val[k],   v1 = s_val[k + 1];
            float2 xa = __half22float2(__ldg(x + c0 + t));
            float2 xb = __half22float2(__ldg(x + c1 + t));
            acc.x += v0 * xa.x; acc.y += v0 * xa.y;
            acc.x += v1 * xb.x; acc.y += v1 * xb.y;
        }
        if (k < n) {
            float v0 = s_val[k];
            float2 xa = __half22float2(__ldg(x + s_col[k] + t));
            acc.x += v0 * xa.x; acc.y += v0 * xa.y;
        }
        __syncthreads();
    }
    size_t o = (size_t)row * 64 + t;  // half2 index
    __half2* outp = (__half2*)(g_xh + (size_t)oi * N_NODES * F);
    if (mode == 0) {
        outp[o] = __float22half2_rn(acc);
    } else {
        const __half2* subp = (const __half2*)(g_xh + (size_t)si * N_NODES * F);
        float2 sb = __half22float2(subp[o]);
        outp[o] = __float22half2_rn(make_float2(2.f * acc.x - sb.x, 2.f * acc.y - sb.y));
        if (mode == 2) {
            __half2* o2p = (__half2*)(g_xh + (size_t)o2i * N_NODES * F);
            o2p[o] = __float22half2_rn(acc);
        }
    }
}

// ---------------- tensor-core GEMM, split-K ----------------
// Per (ks, m): P = A_m[chunk]^T @ Wh[chunk]  -> (128 f x 128 j), fp32 accum.
__global__ void __launch_bounds__(256) gemm_h() {
    __shared__ __align__(16) __half As[32 * 128];
    __shared__ __align__(16) __half Bs[32 * 128];
    int ks = blockIdx.x, m = blockIdx.y;
    const __half* A = g_xh + (size_t)m * N_NODES * F;
    int tid = threadIdx.x, lane = tid & 31, wid = tid >> 5;
    int f0w = (wid >> 1) * 32;   // warp m-range (f)
    int j0w = (wid & 1) * 64;    // warp n-range (j)
    u32 as_base = (u32)__cvta_generic_to_shared(As);
    u32 bs_base = (u32)__cvta_generic_to_shared(Bs);

    float c[2][8][4];
    #pragma unroll
    for (int a = 0; a < 2; a++)
        #pragma unroll
        for (int b = 0; b < 8; b++)
            #pragma unroll
            for (int d = 0; d < 4; d++) c[a][b][d] = 0.f;

    int n0 = ks * KCH;
    // loader: chunks tid and tid+256; chunk = k*16 + cf (k row of 32, cf 16B column group)
    int lk0 = tid >> 4, lcf = tid & 15;
    int lk1 = lk0 + 16;
    int soff0 = lk0 * 128 + ((lcf ^ (lk0 & 7)) << 3);
    int soff1 = lk1 * 128 + ((lcf ^ (lk1 & 7)) << 3);

    uint4 ra0, ra1, rb0, rb1;
    const uint4 zz = make_uint4(0, 0, 0, 0);
    {
        int nb = n0;
        int na = nb + lk0, nbg = nb + lk1;
        if (na < N_NODES) {
            ra0 = *(const uint4*)(A + (size_t)na * F + lcf * 8);
            rb0 = *(const uint4*)(g_wh + (size_t)na * F + lcf * 8);
        } else { ra0 = zz; rb0 = zz; }
        if (nbg < N_NODES) {
            ra1 = *(const uint4*)(A + (size_t)nbg * F + lcf * 8);
            rb1 = *(const uint4*)(g_wh + (size_t)nbg * F + lcf * 8);
        } else { ra1 = zz; rb1 = zz; }
    }

    int g = lane >> 3, i = lane & 7;

    for (int s = 0; s < GSTEPS; s++) {
        __syncthreads();
        *(uint4*)(As + soff0) = ra0; *(uint4*)(Bs + soff0) = rb0;
        *(uint4*)(As + soff1) = ra1; *(uint4*)(Bs + soff1) = rb1;
        __syncthreads();
        if (s + 1 < GSTEPS) {
            int nb = n0 + (s + 1) * 32;
            int na = nb + lk0, nbg = nb + lk1;
            if (na < N_NODES) {
                ra0 = *(const uint4*)(A + (size_t)na * F + lcf * 8);
                rb0 = *(const uint4*)(g_wh + (size_t)na * F + lcf * 8);
            } else { ra0 = zz; rb0 = zz; }
            if (nbg < N_NODES) {
                ra1 = *(const uint4*)(A + (size_t)nbg * F + lcf * 8);
                rb1 = *(const uint4*)(g_wh + (size_t)nbg * F + lcf * 8);
            } else { ra1 = zz; rb1 = zz; }
        }
        #pragma unroll
        for (int kk = 0; kk < 32; kk += 16) {
            u32 a[2][4];
            #pragma unroll
            for (int mt = 0; mt < 2; mt++) {
                int fb = f0w + mt * 16;
                int k = kk + ((g >> 1) << 3) + i;
                int cf = (fb >> 3) + (g & 1);
                u32 addr = as_base + (u32)((k * 128 + ((cf ^ (k & 7)) << 3)) * 2);
                asm volatile("ldmatrix.sync.aligned.m8n8.x4.trans.shared.b16 {%0,%1,%2,%3}, [%4];"
                    : "=r"(a[mt][0]), "=r"(a[mt][1]), "=r"(a[mt][2]), "=r"(a[mt][3]) : "r"(addr));
            }
            u32 b[8][2];
            #pragma unroll
            for (int np = 0; np < 4; np++) {
                int nb = j0w + np * 16;
                int k = kk + ((g & 1) << 3) + i;
                int cf = (nb >> 3) + (g >> 1);
                u32 addr = bs_base + (u32)((k * 128 + ((cf ^ (k & 7)) << 3)) * 2);
                asm volatile("ldmatrix.sync.aligned.m8n8.x4.trans.shared.b16 {%0,%1,%2,%3}, [%4];"
                    : "=r"(b[np * 2][0]), "=r"(b[np * 2][1]), "=r"(b[np * 2 + 1][0]), "=r"(b[np * 2 + 1][1])
                    : "r"(addr));
            }
            #pragma unroll
            for (int mt = 0; mt < 2; mt++)
                #pragma unroll
                for (int nt = 0; nt < 8; nt++)
                    asm volatile("mma.sync.aligned.m16n8k16.row.col.f32.f16.f16.f32 "
                        "{%0,%1,%2,%3}, {%4,%5,%6,%7}, {%8,%9}, {%0,%1,%2,%3};"
                        : "+f"(c[mt][nt][0]), "+f"(c[mt][nt][1]), "+f"(c[mt][nt][2]), "+f"(c[mt][nt][3])
                        : "r"(a[mt][0]), "r"(a[mt][1]), "r"(a[mt][2]), "r"(a[mt][3]),
                          "r"(b[nt][0]), "r"(b[nt][1]));
        }
    }

    float* P = g_part + ((size_t)ks * M_MATS + m) * F * 128;
    int fr = lane >> 2, jc = (lane & 3) * 2;
    #pragma unroll
    for (int mt = 0; mt < 2; mt++)
        #pragma unroll
        for (int nt = 0; nt < 8; nt++) {
            int f = f0w + mt * 16 + fr;
            int j = j0w + nt * 8 + jc;
            *(float2*)(P + (size_t)f * 128 + j) = make_float2(c[mt][nt][0], c[mt][nt][1]);
            *(float2*)(P + (size_t)(f + 8) * 128 + j) = make_float2(c[mt][nt][2], c[mt][nt][3]);
        }
}

// ---------------- reduce partials + bias + GRU epilogue ----------------
__global__ void finish(const float* __restrict__ hx, const float* __restrict__ b_ru,
                       const float* __restrict__ b_c, float* __restrict__ out) {
    int idx = blockIdx.x * blockDim.x + threadIdx.x;  // over 7*128*64
    if (idx >= M_MATS * F * U_DIM) return;
    int j = idx & 63;
    int f = (idx >> 6) & 127;
    int m = idx >> 13;
    float su = __ldg(b_ru + 64 + j);
    float sc = __ldg(b_c + j);
    const float* P = g_part + (size_t)m * F * 128 + (size_t)f * 128;
    #pragma unroll 3
    for (int ks = 0; ks < KSPLIT; ks++) {
        const float* Pk = P + (size_t)ks * M_MATS * F * 128;
        su += Pk[j];
        sc += Pk[64 + j];
    }
    float u = 1.f / (1.f + expf(-su));
    int r = f * M_MATS + m;
    float h = __ldg(hx + r * U_DIM + j);
    out[r * U_DIM + j] = u * h + (1.f - u) * tanhf(sc);
}

// ---------------- launcher ----------------
extern "C" void kernel_launch(void* const* d_in, const int* in_sizes, int n_in,
                              void* d_out, int out_size) {
    const float* inputs   = (const float*)d_in[0];
    const float* hx       = (const float*)d_in[1];
    const float* w_ru     = (const float*)d_in[2];
    const float* b_ru     = (const float*)d_in[3];
    const float* w_c      = (const float*)d_in[4];
    const float* b_c      = (const float*)d_in[5];
    const float* lap_vals = (const float*)d_in[6];
    const float* rw_vals  = (const float*)d_in[7];
    const int*   lap_rows = (const int*)d_in[8];
    const int*   lap_cols = (const int*)d_in[9];
    const int*   rw_rows  = (const int*)d_in[10];
    const int*   rw_cols  = (const int*)d_in[11];
    float* out = (float*)d_out;

    const int TB = 256;
    const int gE = (NNZ + TB - 1) / TB;

    // CSR build for both matrices
    zero2<<<(2 * N_NODES + TB - 1) / TB, TB>>>();
    hist2<<<dim3(gE, 2), TB>>>(lap_rows, rw_rows);
    scan2<<<2, 1024>>>();
    zero2<<<(2 * N_NODES + TB - 1) / TB, TB>>>();
    scatter2<<<dim3(gE, 2), TB>>>(lap_rows, lap_cols, lap_vals, rw_rows, rw_cols, rw_vals);

    // x0 + weight prep
    build_x0<<<(N_NODES * 64 + TB - 1) / TB, TB>>>(inputs);
    wprep<<<(N_NODES * F + TB - 1) / TB, TB>>>(w_ru, w_c);

    // SpMM chain:
    // xs1 = L x0; xs2 = 2 L xs1 - x0; xs3 = R xs1; t = R xs3 (xs5 = t, xs4 = 2t - xs1); xs6 = 2 R xs5 - xs3
    spmm_h<<<N_NODES, 64>>>(0, 0, 1, 0, 0, 0);
    spmm_h<<<N_NODES, 64>>>(0, 1, 2, 0, 0, 1);
    spmm_h<<<N_NODES, 64>>>(1, 1, 3, 0, 0, 0);
    spmm_h<<<N_NODES, 64>>>(1, 3, 4, 1, 5, 2);
    spmm_h<<<N_NODES, 64>>>(1, 5, 6, 3, 0, 1);

    // tensor-core GEMM + fused epilogue
    gemm_h<<<dim3(KSPLIT, M_MATS), 256>>>();
    finish<<<(M_MATS * F * U_DIM + TB - 1) / TB, TB>>>(hx, b_ru, b_c, out);
}

// round 5
// speedup vs baseline: 2.3749x; 1.1219x over previous
#include <cuda_runtime.h>
#include <cuda_fp16.h>
#include <cstdint>

#define N_NODES 50000
#define NNZ     1600000
#define F       128        // D*B
#define M_MATS  7
#define U_DIM   64
#define KSPLIT  21
#define KCH     2400       // 21*2400 = 50400 >= 50000, padded with zeros
#define GSTEPS  (KCH / 32) // 75

typedef unsigned int u32;

// ---------------- device scratch (static, no allocation) ----------------
__device__ __half g_xh[(size_t)M_MATS * N_NODES * F];   // xs[0..6] in fp16, (N, F) each
__device__ __half g_wh[(size_t)N_NODES * F];            // [n][j]: j<64 -> w_ru[:,64+j], j>=64 -> w_c[:,j-64]
__device__ int2   g_csr[2][NNZ];                        // {col, val_bits}
__device__ int    g_rowptr[2][N_NODES + 1];
__device__ int    g_next[2][N_NODES];                   // scatter cursors (copy of rowptr)
__device__ int    g_cnt[2][N_NODES];
__device__ float  g_part[(size_t)KSPLIT * M_MATS * F * 128];

// ---------------- CSR build ----------------
__global__ void zero2() {
    int i = blockIdx.x * blockDim.x + threadIdx.x;
    if (i < 2 * N_NODES) ((int*)g_cnt)[i] = 0;
}

__global__ void hist2(const int* __restrict__ lr, const int* __restrict__ rr) {
    int e = blockIdx.x * blockDim.x + threadIdx.x;
    if (e >= NNZ) return;
    int sel = blockIdx.y;
    const int* rows = sel ? rr : lr;
    atomicAdd(&g_cnt[sel][rows[e]], 1);
}

// one block per sel; exclusive scan of g_cnt[sel] -> g_rowptr[sel] (+ g_next copy)
__global__ void scan2() {
    int sel = blockIdx.x;
    int* rowptr = g_rowptr[sel];
    int* nxt = g_next[sel];
    const int* cnt = g_cnt[sel];
    __shared__ int warp_sums[32];
    __shared__ int s_carry;
    int tid = threadIdx.x;  // 1024 threads
    if (tid == 0) s_carry = 0;
    __syncthreads();
    for (int base = 0; base < N_NODES; base += 1024) {
        int i = base + tid;
        int v = (i < N_NODES) ? cnt[i] : 0;
        int x = v;
        #pragma unroll
        for (int o = 1; o < 32; o <<= 1) {
            int y = __shfl_up_sync(0xffffffffu, x, o);
            if ((tid & 31) >= o) x += y;
        }
        if ((tid & 31) == 31) warp_sums[tid >> 5] = x;
        __syncthreads();
        if (tid < 32) {
            int w = warp_sums[tid];
            #pragma unroll
            for (int o = 1; o < 32; o <<= 1) {
                int y = __shfl_up_sync(0xffffffffu, w, o);
                if (tid >= o) w += y;
            }
            warp_sums[tid] = w;
        }
        __syncthreads();
        int warp_off = (tid >= 32) ? warp_sums[(tid >> 5) - 1] : 0;
        int incl = x + warp_off;
        int carry = s_carry;
        if (i < N_NODES) {
            int ex = carry + incl - v;
            rowptr[i] = ex;
            nxt[i] = ex;
        }
        __syncthreads();
        if (tid == 1023) s_carry = carry + incl;
        __syncthreads();
    }
    if (tid == 0) rowptr[N_NODES] = NNZ;
}

__global__ void scatter2(const int* __restrict__ lr, const int* __restrict__ lc, const float* __restrict__ lv,
                         const int* __restrict__ rr, const int* __restrict__ rc, const float* __restrict__ rv) {
    int e = blockIdx.x * blockDim.x + threadIdx.x;
    if (e >= NNZ) return;
    int sel = blockIdx.y;
    const int* rows = sel ? rr : lr;
    const int* cols = sel ? rc : lc;
    const float* vals = sel ? rv : lv;
    int r = rows[e];
    int p = atomicAdd(&g_next[sel][r], 1);
    g_csr[sel][p] = make_int2(cols[e], __float_as_int(vals[e]));
}

// ---------------- fused prep: x0 transpose + merged fp16 weights ----------------
__global__ void prep(const float* __restrict__ inputs,
                     const float* __restrict__ w_ru, const float* __restrict__ w_c) {
    int idx = blockIdx.x * blockDim.x + threadIdx.x;
    if (idx < N_NODES * 64) {
        int b = idx & 63;
        int n = idx >> 6;
        float2 v = __ldg((const float2*)inputs + (size_t)b * N_NODES + n);
        g_xh[(size_t)n * F + b] = __float2half_rn(v.x);
        g_xh[(size_t)n * F + 64 + b] = __float2half_rn(v.y);
    } else {
        int id2 = idx - N_NODES * 64;
        if (id2 >= N_NODES * F) return;
        int n = id2 >> 7, j = id2 & 127;
        float v = (j < 64) ? __ldg(w_ru + (size_t)n * 128 + 64 + j)
                           : __ldg(w_c + (size_t)n * 64 + (j - 64));
        g_wh[id2] = __float2half_rn(v);
    }
}

// ---------------- SpMM body: warp per row, shuffle-broadcast edges ----------------
// lane owns 4 consecutive fp16 columns (one uint2 = 8B). fp32 accumulation.
// mode 0: out = acc ; mode 1: out = 2*acc - sub ; mode 2: mode1 + out2 = acc
__device__ __forceinline__ void spmm_body(int mat, int xi, int oi, int si, int o2i, int mode,
                                          int row, int lane) {
    const uint2* xb = (const uint2*)(g_xh + (size_t)xi * N_NODES * F);
    int e0 = __ldg(&g_rowptr[mat][row]);
    int e1 = __ldg(&g_rowptr[mat][row + 1]);
    float4 acc = make_float4(0.f, 0.f, 0.f, 0.f);
    for (int base = e0; base < e1; base += 32) {
        int n = e1 - base;
        if (n > 32) n = 32;
        int colv = 0; float valv = 0.f;
        if (lane < n) {
            int2 cv = __ldg(&g_csr[mat][base + lane]);
            colv = cv.x << 5;  // uint2 index of row start (32 uint2 per row)
            valv = __int_as_float(cv.y);
        }
        int k = 0;
        for (; k + 2 <= n; k += 2) {
            int   c0 = __shfl_sync(0xffffffffu, colv, k);
            int   c1 = __shfl_sync(0xffffffffu, colv, k + 1);
            float v0 = __shfl_sync(0xffffffffu, valv, k);
            float v1 = __shfl_sync(0xffffffffu, valv, k + 1);
            uint2 p0 = __ldg(xb + c0 + lane);
            uint2 p1 = __ldg(xb + c1 + lane);
            float2 a0 = __half22float2(*(__half2*)&p0.x);
            float2 b0 = __half22float2(*(__half2*)&p0.y);
            acc.x += v0 * a0.x; acc.y += v0 * a0.y; acc.z += v0 * b0.x; acc.w += v0 * b0.y;
            float2 a1 = __half22float2(*(__half2*)&p1.x);
            float2 b1 = __half22float2(*(__half2*)&p1.y);
            acc.x += v1 * a1.x; acc.y += v1 * a1.y; acc.z += v1 * b1.x; acc.w += v1 * b1.y;
        }
        if (k < n) {
            int   c0 = __shfl_sync(0xffffffffu, colv, k);
            float v0 = __shfl_sync(0xffffffffu, valv, k);
            uint2 p0 = __ldg(xb + c0 + lane);
            float2 a0 = __half22float2(*(__half2*)&p0.x);
            float2 b0 = __half22float2(*(__half2*)&p0.y);
            acc.x += v0 * a0.x; acc.y += v0 * a0.y; acc.z += v0 * b0.x; acc.w += v0 * b0.y;
        }
    }
    size_t o = (size_t)row * 32 + lane;
    uint2* outp = (uint2*)(g_xh + (size_t)oi * N_NODES * F);
    if (mode == 0) {
        __half2 h0 = __floats2half2_rn(acc.x, acc.y);
        __half2 h1 = __floats2half2_rn(acc.z, acc.w);
        uint2 pk; pk.x = *(u32*)&h0; pk.y = *(u32*)&h1;
        outp[o] = pk;
    } else {
        const uint2* subp = (const uint2*)(g_xh + (size_t)si * N_NODES * F);
        uint2 sp = __ldg(subp + o);
        float2 s0 = __half22float2(*(__half2*)&sp.x);
        float2 s1 = __half22float2(*(__half2*)&sp.y);
        __half2 h0 = __floats2half2_rn(2.f * acc.x - s0.x, 2.f * acc.y - s0.y);
        __half2 h1 = __floats2half2_rn(2.f * acc.z - s1.x, 2.f * acc.w - s1.y);
        uint2 pk; pk.x = *(u32*)&h0; pk.y = *(u32*)&h1;
        outp[o] = pk;
        if (mode == 2) {
            uint2* o2p = (uint2*)(g_xh + (size_t)o2i * N_NODES * F);
            __half2 g0 = __floats2half2_rn(acc.x, acc.y);
            __half2 g1 = __floats2half2_rn(acc.z, acc.w);
            uint2 pk2; pk2.x = *(u32*)&g0; pk2.y = *(u32*)&g1;
            o2p[o] = pk2;
        }
    }
}

__global__ void __launch_bounds__(256) spmm_w(int mat, int xi, int oi, int si, int o2i, int mode) {
    int row = (blockIdx.x << 3) + (threadIdx.x >> 5);
    if (row >= N_NODES) return;
    spmm_body(mat, xi, oi, si, o2i, mode, row, threadIdx.x & 31);
}

// combined: y=0 -> xs2 = 2 L xs1 - x0 ; y=1 -> xs3 = R xs1
__global__ void __launch_bounds__(256) spmm_dual() {
    int row = (blockIdx.x << 3) + (threadIdx.x >> 5);
    if (row >= N_NODES) return;
    int lane = threadIdx.x & 31;
    if (blockIdx.y == 0) spmm_body(0, 1, 2, 0, 0, 1, row, lane);
    else                 spmm_body(1, 1, 3, 0, 0, 0, row, lane);
}

// ---------------- tensor-core GEMM, split-K ----------------
__global__ void __launch_bounds__(256) gemm_h() {
    __shared__ __align__(16) __half As[32 * 128];
    __shared__ __align__(16) __half Bs[32 * 128];
    int ks = blockIdx.x, m = blockIdx.y;
    const __half* A = g_xh + (size_t)m * N_NODES * F;
    int tid = threadIdx.x, lane = tid & 31, wid = tid >> 5;
    int f0w = (wid >> 1) * 32;   // warp m-range (f)
    int j0w = (wid & 1) * 64;    // warp n-range (j)
    u32 as_base = (u32)__cvta_generic_to_shared(As);
    u32 bs_base = (u32)__cvta_generic_to_shared(Bs);

    float c[2][8][4];
    #pragma unroll
    for (int a = 0; a < 2; a++)
        #pragma unroll
        for (int b = 0; b < 8; b++)
            #pragma unroll
            for (int d = 0; d < 4; d++) c[a][b][d] = 0.f;

    int n0 = ks * KCH;
    int lk0 = tid >> 4, lcf = tid & 15;
    int lk1 = lk0 + 16;
    int soff0 = lk0 * 128 + ((lcf ^ (lk0 & 7)) << 3);
    int soff1 = lk1 * 128 + ((lcf ^ (lk1 & 7)) << 3);

    uint4 ra0, ra1, rb0, rb1;
    const uint4 zz = make_uint4(0, 0, 0, 0);
    {
        int na = n0 + lk0, nbg = n0 + lk1;
        if (na < N_NODES) {
            ra0 = *(const uint4*)(A + (size_t)na * F + lcf * 8);
            rb0 = *(const uint4*)(g_wh + (size_t)na * F + lcf * 8);
        } else { ra0 = zz; rb0 = zz; }
        if (nbg < N_NODES) {
            ra1 = *(const uint4*)(A + (size_t)nbg * F + lcf * 8);
            rb1 = *(const uint4*)(g_wh + (size_t)nbg * F + lcf * 8);
        } else { ra1 = zz; rb1 = zz; }
    }

    int g = lane >> 3, i = lane & 7;

    for (int s = 0; s < GSTEPS; s++) {
        __syncthreads();
        *(uint4*)(As + soff0) = ra0; *(uint4*)(Bs + soff0) = rb0;
        *(uint4*)(As + soff1) = ra1; *(uint4*)(Bs + soff1) = rb1;
        __syncthreads();
        if (s + 1 < GSTEPS) {
            int nb = n0 + (s + 1) * 32;
            int na = nb + lk0, nbg = nb + lk1;
            if (na < N_NODES) {
                ra0 = *(const uint4*)(A + (size_t)na * F + lcf * 8);
                rb0 = *(const uint4*)(g_wh + (size_t)na * F + lcf * 8);
            } else { ra0 = zz; rb0 = zz; }
            if (nbg < N_NODES) {
                ra1 = *(const uint4*)(A + (size_t)nbg * F + lcf * 8);
                rb1 = *(const uint4*)(g_wh + (size_t)nbg * F + lcf * 8);
            } else { ra1 = zz; rb1 = zz; }
        }
        #pragma unroll
        for (int kk = 0; kk < 32; kk += 16) {
            u32 a[2][4];
            #pragma unroll
            for (int mt = 0; mt < 2; mt++) {
                int fb = f0w + mt * 16;
                int k = kk + ((g >> 1) << 3) + i;
                int cf = (fb >> 3) + (g & 1);
                u32 addr = as_base + (u32)((k * 128 + ((cf ^ (k & 7)) << 3)) * 2);
                asm volatile("ldmatrix.sync.aligned.m8n8.x4.trans.shared.b16 {%0,%1,%2,%3}, [%4];"
                    : "=r"(a[mt][0]), "=r"(a[mt][1]), "=r"(a[mt][2]), "=r"(a[mt][3]) : "r"(addr));
            }
            u32 b[8][2];
            #pragma unroll
            for (int np = 0; np < 4; np++) {
                int nb = j0w + np * 16;
                int k = kk + ((g & 1) << 3) + i;
                int cf = (nb >> 3) + (g >> 1);
                u32 addr = bs_base + (u32)((k * 128 + ((cf ^ (k & 7)) << 3)) * 2);
                asm volatile("ldmatrix.sync.aligned.m8n8.x4.trans.shared.b16 {%0,%1,%2,%3}, [%4];"
                    : "=r"(b[np * 2][0]), "=r"(b[np * 2][1]), "=r"(b[np * 2 + 1][0]), "=r"(b[np * 2 + 1][1])
                    : "r"(addr));
            }
            #pragma unroll
            for (int mt = 0; mt < 2; mt++)
                #pragma unroll
                for (int nt = 0; nt < 8; nt++)
                    asm volatile("mma.sync.aligned.m16n8k16.row.col.f32.f16.f16.f32 "
                        "{%0,%1,%2,%3}, {%4,%5,%6,%7}, {%8,%9}, {%0,%1,%2,%3};"
                        : "+f"(c[mt][nt][0]), "+f"(c[mt][nt][1]), "+f"(c[mt][nt][2]), "+f"(c[mt][nt][3])
                        : "r"(a[mt][0]), "r"(a[mt][1]), "r"(a[mt][2]), "r"(a[mt][3]),
                          "r"(b[nt][0]), "r"(b[nt][1]));
        }
    }

    float* P = g_part + ((size_t)ks * M_MATS + m) * F * 128;
    int fr = lane >> 2, jc = (lane & 3) * 2;
    #pragma unroll
    for (int mt = 0; mt < 2; mt++)
        #pragma unroll
        for (int nt = 0; nt < 8; nt++) {
            int f = f0w + mt * 16 + fr;
            int j = j0w + nt * 8 + jc;
            *(float2*)(P + (size_t)f * 128 + j) = make_float2(c[mt][nt][0], c[mt][nt][1]);
            *(float2*)(P + (size_t)(f + 8) * 128 + j) = make_float2(c[mt][nt][2], c[mt][nt][3]);
        }
}

// ---------------- reduce partials + bias + GRU epilogue ----------------
__global__ void finish(const float* __restrict__ hx, const float* __restrict__ b_ru,
                       const float* __restrict__ b_c, float* __restrict__ out) {
    int idx = blockIdx.x * blockDim.x + threadIdx.x;  // over 7*128*64
    if (idx >= M_MATS * F * U_DIM) return;
    int j = idx & 63;
    int f = (idx >> 6) & 127;
    int m = idx >> 13;
    float su = __ldg(b_ru + 64 + j);
    float sc = __ldg(b_c + j);
    const float* P = g_part + (size_t)m * F * 128 + (size_t)f * 128;
    #pragma unroll 3
    for (int ks = 0; ks < KSPLIT; ks++) {
        const float* Pk = P + (size_t)ks * M_MATS * F * 128;
        su += Pk[j];
        sc += Pk[64 + j];
    }
    float u = 1.f / (1.f + expf(-su));
    int r = f * M_MATS + m;
    float h = __ldg(hx + r * U_DIM + j);
    out[r * U_DIM + j] = u * h + (1.f - u) * tanhf(sc);
}

// ---------------- launcher ----------------
extern "C" void kernel_launch(void* const* d_in, const int* in_sizes, int n_in,
                              void* d_out, int out_size) {
    const float* inputs   = (const float*)d_in[0];
    const float* hx       = (const float*)d_in[1];
    const float* w_ru     = (const float*)d_in[2];
    const float* b_ru     = (const float*)d_in[3];
    const float* w_c      = (const float*)d_in[4];
    const float* b_c      = (const float*)d_in[5];
    const float* lap_vals = (const float*)d_in[6];
    const float* rw_vals  = (const float*)d_in[7];
    const int*   lap_rows = (const int*)d_in[8];
    const int*   lap_cols = (const int*)d_in[9];
    const int*   rw_rows  = (const int*)d_in[10];
    const int*   rw_cols  = (const int*)d_in[11];
    float* out = (float*)d_out;

    const int TB = 256;
    const int gE = (NNZ + TB - 1) / TB;
    const int gSp = (N_NODES + 7) / 8;

    // CSR build (4 launches)
    zero2<<<(2 * N_NODES + TB - 1) / TB, TB>>>();
    hist2<<<dim3(gE, 2), TB>>>(lap_rows, rw_rows);
    scan2<<<2, 1024>>>();
    scatter2<<<dim3(gE, 2), TB>>>(lap_rows, lap_cols, lap_vals, rw_rows, rw_cols, rw_vals);

    // x0 transpose + weight conversion (1 launch)
    prep<<<(N_NODES * 192 + TB - 1) / TB, TB>>>(inputs, w_ru, w_c);

    // SpMM chain (4 phases):
    // xs1 = L x0; {xs2 = 2 L xs1 - x0, xs3 = R xs1}; t = R xs3 (xs5=t, xs4=2t-xs1); xs6 = 2 R xs5 - xs3
    spmm_w<<<gSp, 256>>>(0, 0, 1, 0, 0, 0);          // launch #6 — ncu target
    spmm_dual<<<dim3(gSp, 2), 256>>>();
    spmm_w<<<gSp, 256>>>(1, 3, 4, 1, 5, 2);
    spmm_w<<<gSp, 256>>>(1, 5, 6, 3, 0, 1);

    // tensor-core GEMM + fused epilogue
    gemm_h<<<dim3(KSPLIT, M_MATS), 256>>>();
    finish<<<(M_MATS * F * U_DIM + TB - 1) / TB, TB>>>(hx, b_ru, b_c, out);
}

// round 8
// speedup vs baseline: 2.8373x; 1.1947x over previous
#include <cuda_runtime.h>
#include <cuda_fp16.h>
#include <cstdint>

#define N_NODES 50000
#define NNZ     1600000
#define F       128        // D*B
#define M_MATS  7
#define U_DIM   64
#define KSPLIT  21
#define KCH     2400       // 21*2400 = 50400 >= 50000, padded with zeros
#define GSTEPS  (KCH / 32) // 75

typedef unsigned int u32;

// ---------------- device scratch (static, no allocation; 16B-aligned for vector casts) ----------------
__device__ __align__(16) __half g_xh[(size_t)M_MATS * N_NODES * F];   // xs[0..6] in fp16, (N, F) each
__device__ __align__(16) __half g_wh[(size_t)N_NODES * F];            // [n][j]: j<64 -> w_ru[:,64+j], j>=64 -> w_c[:,j-64]
__device__ __align__(16) int2   g_csr[2][NNZ];                        // {col, val_bits}
__device__ __align__(16) int    g_rowptr[2][N_NODES + 4];             // padded so int4 stores stay in-bounds
__device__ __align__(16) int    g_next[2][N_NODES];                   // scatter cursors (copy of rowptr)
__device__ __align__(16) int    g_cnt[2][N_NODES];
__device__ __align__(16) float  g_part[(size_t)KSPLIT * M_MATS * F * 128];

// ---------------- CSR build ----------------
__global__ void zero2() {
    int i = blockIdx.x * blockDim.x + threadIdx.x;
    if (i < 2 * N_NODES) {
        g_cnt[0][0] = g_cnt[0][0];  // no-op to keep layout; real zero below
    }
    if (i < N_NODES) { g_cnt[0][i] = 0; g_cnt[1][i] = 0; }
}

// scalar reads of harness buffers (alignment not guaranteed), 4 edges per thread
__global__ void hist2(const int* __restrict__ lr, const int* __restrict__ rr) {
    int e0 = (blockIdx.x * blockDim.x + threadIdx.x) * 4;
    if (e0 >= NNZ) return;
    int sel = blockIdx.y;
    const int* rows = sel ? rr : lr;
    #pragma unroll
    for (int q = 0; q < 4; q++) {
        atomicAdd(&g_cnt[sel][__ldg(rows + e0 + q)], 1);
    }
}

// one block per sel; exclusive scan of g_cnt[sel] -> g_rowptr[sel] (+ g_next copy)
// int4-vectorized over our own aligned arrays
__global__ void scan2() {
    int sel = blockIdx.x;
    int4* rowptr4 = (int4*)g_rowptr[sel];
    int4* nxt4 = (int4*)g_next[sel];
    const int4* cnt4 = (const int4*)g_cnt[sel];
    __shared__ int warp_sums[32];
    __shared__ int s_carry;
    int tid = threadIdx.x;  // 1024
    if (tid == 0) s_carry = 0;
    __syncthreads();
    const int NQ = N_NODES / 4;  // 12500
    for (int base = 0; base < NQ; base += 1024) {
        int i = base + tid;
        int4 v = (i < NQ) ? cnt4[i] : make_int4(0, 0, 0, 0);
        int s = v.x + v.y + v.z + v.w;
        int x = s;
        #pragma unroll
        for (int o = 1; o < 32; o <<= 1) {
            int y = __shfl_up_sync(0xffffffffu, x, o);
            if ((tid & 31) >= o) x += y;
        }
        if ((tid & 31) == 31) warp_sums[tid >> 5] = x;
        __syncthreads();
        if (tid < 32) {
            int w = warp_sums[tid];
            #pragma unroll
            for (int o = 1; o < 32; o <<= 1) {
                int y = __shfl_up_sync(0xffffffffu, w, o);
                if (tid >= o) w += y;
            }
            warp_sums[tid] = w;
        }
        __syncthreads();
        int warp_off = (tid >= 32) ? warp_sums[(tid >> 5) - 1] : 0;
        int incl = x + warp_off;
        int carry = s_carry;
        if (i < NQ) {
            int p = carry + incl - s;  // exclusive prefix for element 4i
            int4 o4;
            o4.x = p;
            o4.y = p + v.x;
            o4.z = p + v.x + v.y;
            o4.w = p + v.x + v.y + v.z;
            rowptr4[i] = o4;
            nxt4[i] = o4;
        }
        __syncthreads();
        if (tid == 1023) s_carry = carry + incl;
        __syncthreads();
    }
    if (tid == 0) g_rowptr[sel][N_NODES] = NNZ;
}

// scalar reads of harness buffers; atomic bump cursors; 4 edges per thread
__global__ void scatter2(const int* __restrict__ lr, const int* __restrict__ lc, const float* __restrict__ lv,
                         const int* __restrict__ rr, const int* __restrict__ rc, const float* __restrict__ rv) {
    int e0 = (blockIdx.x * blockDim.x + threadIdx.x) * 4;
    if (e0 >= NNZ) return;
    int sel = blockIdx.y;
    const int* rows = sel ? rr : lr;
    const int* cols = sel ? rc : lc;
    const float* vals = sel ? rv : lv;
    #pragma unroll
    for (int q = 0; q < 4; q++) {
        int e = e0 + q;
        int r = __ldg(rows + e);
        int p = atomicAdd(&g_next[sel][r], 1);
        g_csr[sel][p] = make_int2(__ldg(cols + e), __float_as_int(__ldg(vals + e)));
    }
}

// ---------------- fused prep: x0 transpose + merged fp16 weights ----------------
__global__ void prep(const float* __restrict__ inputs,
                     const float* __restrict__ w_ru, const float* __restrict__ w_c) {
    int idx = blockIdx.x * blockDim.x + threadIdx.x;
    if (idx < N_NODES * 64) {
        int b = idx & 63;
        int n = idx >> 6;
        // inputs (B, N, D): scalar loads (alignment-safe)
        float vx = __ldg(inputs + ((size_t)b * N_NODES + n) * 2);
        float vy = __ldg(inputs + ((size_t)b * N_NODES + n) * 2 + 1);
        g_xh[(size_t)n * F + b] = __float2half_rn(vx);
        g_xh[(size_t)n * F + 64 + b] = __float2half_rn(vy);
    } else {
        int id2 = idx - N_NODES * 64;
        if (id2 >= N_NODES * F) return;
        int n = id2 >> 7, j = id2 & 127;
        float v = (j < 64) ? __ldg(w_ru + (size_t)n * 128 + 64 + j)
                           : __ldg(w_c + (size_t)n * 64 + (j - 64));
        g_wh[id2] = __float2half_rn(v);
    }
}

// ---------------- SpMM body: half-warp per row, LDG.128 gathers ----------------
// Warp serves rows (pair, pair+1): lanes 0-15 -> row pair, lanes 16-31 -> row pair+1.
// Each lane owns 8 consecutive fp16 columns (one uint4 = 16B).
// mode 0: out = acc ; mode 1: out = 2*acc - sub ; mode 2: mode1 + out2 = acc
__device__ __forceinline__ void spmm_body(int mat, int xi, int oi, int si, int o2i, int mode,
                                          int row, int lane) {
    int hl = lane & 15;          // lane within half-warp
    const uint4* xb = (const uint4*)(g_xh + (size_t)xi * N_NODES * F);
    int e0 = __ldg(&g_rowptr[mat][row]);
    int e1 = __ldg(&g_rowptr[mat][row + 1]);
    int deg = e1 - e0;
    int odeg = __shfl_xor_sync(0xffffffffu, deg, 16);
    int maxdeg = deg > odeg ? deg : odeg;
    float ax = 0.f, ay = 0.f, az = 0.f, aw = 0.f, bx = 0.f, by = 0.f, bz = 0.f, bw = 0.f;
    for (int base = 0; base < maxdeg; base += 16) {
        int colv = 0; float valv = 0.f;
        if (base + hl < deg) {
            int2 cv = __ldg(&g_csr[mat][e0 + base + hl]);
            colv = cv.x << 4;    // uint4 index of gathered row start (16 uint4 per row)
            valv = __int_as_float(cv.y);
        }
        int kmax = maxdeg - base; if (kmax > 16) kmax = 16;
        int k = 0;
        for (; k + 2 <= kmax; k += 2) {
            int   c0 = __shfl_sync(0xffffffffu, colv, k, 16);
            int   c1 = __shfl_sync(0xffffffffu, colv, k + 1, 16);
            float v0 = __shfl_sync(0xffffffffu, valv, k, 16);
            float v1 = __shfl_sync(0xffffffffu, valv, k + 1, 16);
            uint4 p0 = __ldg(xb + c0 + hl);
            uint4 p1 = __ldg(xb + c1 + hl);
            float2 q0 = __half22float2(*(__half2*)&p0.x);
            float2 q1 = __half22float2(*(__half2*)&p0.y);
            float2 q2 = __half22float2(*(__half2*)&p0.z);
            float2 q3 = __half22float2(*(__half2*)&p0.w);
            ax += v0 * q0.x; ay += v0 * q0.y; az += v0 * q1.x; aw += v0 * q1.y;
            bx += v0 * q2.x; by += v0 * q2.y; bz += v0 * q3.x; bw += v0 * q3.y;
            float2 r0 = __half22float2(*(__half2*)&p1.x);
            float2 r1 = __half22float2(*(__half2*)&p1.y);
            float2 r2 = __half22float2(*(__half2*)&p1.z);
            float2 r3 = __half22float2(*(__half2*)&p1.w);
            ax += v1 * r0.x; ay += v1 * r0.y; az += v1 * r1.x; aw += v1 * r1.y;
            bx += v1 * r2.x; by += v1 * r2.y; bz += v1 * r3.x; bw += v1 * r3.y;
        }
        if (k < kmax) {
            int   c0 = __shfl_sync(0xffffffffu, colv, k, 16);
            float v0 = __shfl_sync(0xffffffffu, valv, k, 16);
            uint4 p0 = __ldg(xb + c0 + hl);
            float2 q0 = __half22float2(*(__half2*)&p0.x);
            float2 q1 = __half22float2(*(__half2*)&p0.y);
            float2 q2 = __half22float2(*(__half2*)&p0.z);
            float2 q3 = __half22float2(*(__half2*)&p0.w);
            ax += v0 * q0.x; ay += v0 * q0.y; az += v0 * q1.x; aw += v0 * q1.y;
            bx += v0 * q2.x; by += v0 * q2.y; bz += v0 * q3.x; bw += v0 * q3.y;
        }
    }
    size_t o = (size_t)row * 16 + hl;  // uint4 index
    uint4* outp = (uint4*)(g_xh + (size_t)oi * N_NODES * F);
    if (mode == 0) {
        __half2 h0 = __floats2half2_rn(ax, ay);
        __half2 h1 = __floats2half2_rn(az, aw);
        __half2 h2 = __floats2half2_rn(bx, by);
        __half2 h3 = __floats2half2_rn(bz, bw);
        uint4 pk; pk.x = *(u32*)&h0; pk.y = *(u32*)&h1; pk.z = *(u32*)&h2; pk.w = *(u32*)&h3;
        outp[o] = pk;
    } else {
        const uint4* subp = (const uint4*)(g_xh + (size_t)si * N_NODES * F);
        uint4 sp = __ldg(subp + o);
        float2 s0 = __half22float2(*(__half2*)&sp.x);
        float2 s1 = __half22float2(*(__half2*)&sp.y);
        float2 s2 = __half22float2(*(__half2*)&sp.z);
        float2 s3 = __half22float2(*(__half2*)&sp.w);
        __half2 h0 = __floats2half2_rn(2.f * ax - s0.x, 2.f * ay - s0.y);
        __half2 h1 = __floats2half2_rn(2.f * az - s1.x, 2.f * aw - s1.y);
        __half2 h2 = __floats2half2_rn(2.f * bx - s2.x, 2.f * by - s2.y);
        __half2 h3 = __floats2half2_rn(2.f * bz - s3.x, 2.f * bw - s3.y);
        uint4 pk; pk.x = *(u32*)&h0; pk.y = *(u32*)&h1; pk.z = *(u32*)&h2; pk.w = *(u32*)&h3;
        outp[o] = pk;
        if (mode == 2) {
            uint4* o2p = (uint4*)(g_xh + (size_t)o2i * N_NODES * F);
            __half2 g0 = __floats2half2_rn(ax, ay);
            __half2 g1 = __floats2half2_rn(az, aw);
            __half2 g2 = __floats2half2_rn(bx, by);
            __half2 g3 = __floats2half2_rn(bz, bw);
            uint4 pk2; pk2.x = *(u32*)&g0; pk2.y = *(u32*)&g1; pk2.z = *(u32*)&g2; pk2.w = *(u32*)&g3;
            o2p[o] = pk2;
        }
    }
}

// block = 256 threads = 8 warps = 16 rows; grid = 3125 exact
__global__ void __launch_bounds__(256) spmm_w(int mat, int xi, int oi, int si, int o2i, int mode) {
    int lane = threadIdx.x & 31;
    int row = (blockIdx.x << 4) + ((threadIdx.x >> 5) << 1) + (lane >> 4);
    spmm_body(mat, xi, oi, si, o2i, mode, row, lane);
}

// combined: y=0 -> xs2 = 2 L xs1 - x0 ; y=1 -> xs3 = R xs1
__global__ void __launch_bounds__(256) spmm_dual() {
    int lane = threadIdx.x & 31;
    int row = (blockIdx.x << 4) + ((threadIdx.x >> 5) << 1) + (lane >> 4);
    if (blockIdx.y == 0) spmm_body(0, 1, 2, 0, 0, 1, row, lane);
    else                 spmm_body(1, 1, 3, 0, 0, 0, row, lane);
}

// ---------------- tensor-core GEMM, split-K ----------------
__global__ void __launch_bounds__(256) gemm_h() {
    __shared__ __align__(16) __half As[32 * 128];
    __shared__ __align__(16) __half Bs[32 * 128];
    int ks = blockIdx.x, m = blockIdx.y;
    const __half* A = g_xh + (size_t)m * N_NODES * F;
    int tid = threadIdx.x, lane = tid & 31, wid = tid >> 5;
    int f0w = (wid >> 1) * 32;   // warp m-range (f)
    int j0w = (wid & 1) * 64;    // warp n-range (j)
    u32 as_base = (u32)__cvta_generic_to_shared(As);
    u32 bs_base = (u32)__cvta_generic_to_shared(Bs);

    float c[2][8][4];
    #pragma unroll
    for (int a = 0; a < 2; a++)
        #pragma unroll
        for (int b = 0; b < 8; b++)
            #pragma unroll
            for (int d = 0; d < 4; d++) c[a][b][d] = 0.f;

    int n0 = ks * KCH;
    int lk0 = tid >> 4, lcf = tid & 15;
    int lk1 = lk0 + 16;
    int soff0 = lk0 * 128 + ((lcf ^ (lk0 & 7)) << 3);
    int soff1 = lk1 * 128 + ((lcf ^ (lk1 & 7)) << 3);

    uint4 ra0, ra1, rb0, rb1;
    const uint4 zz = make_uint4(0, 0, 0, 0);
    {
        int na = n0 + lk0, nbg = n0 + lk1;
        if (na < N_NODES) {
            ra0 = *(const uint4*)(A + (size_t)na * F + lcf * 8);
            rb0 = *(const uint4*)(g_wh + (size_t)na * F + lcf * 8);
        } else { ra0 = zz; rb0 = zz; }
        if (nbg < N_NODES) {
            ra1 = *(const uint4*)(A + (size_t)nbg * F + lcf * 8);
            rb1 = *(const uint4*)(g_wh + (size_t)nbg * F + lcf * 8);
        } else { ra1 = zz; rb1 = zz; }
    }

    int g = lane >> 3, i = lane & 7;

    for (int s = 0; s < GSTEPS; s++) {
        __syncthreads();
        *(uint4*)(As + soff0) = ra0; *(uint4*)(Bs + soff0) = rb0;
        *(uint4*)(As + soff1) = ra1; *(uint4*)(Bs + soff1) = rb1;
        __syncthreads();
        if (s + 1 < GSTEPS) {
            int nb = n0 + (s + 1) * 32;
            int na = nb + lk0, nbg = nb + lk1;
            if (na < N_NODES) {
                ra0 = *(const uint4*)(A + (size_t)na * F + lcf * 8);
                rb0 = *(const uint4*)(g_wh + (size_t)na * F + lcf * 8);
            } else { ra0 = zz; rb0 = zz; }
            if (nbg < N_NODES) {
                ra1 = *(const uint4*)(A + (size_t)nbg * F + lcf * 8);
                rb1 = *(const uint4*)(g_wh + (size_t)nbg * F + lcf * 8);
            } else { ra1 = zz; rb1 = zz; }
        }
        #pragma unroll
        for (int kk = 0; kk < 32; kk += 16) {
            u32 a[2][4];
            #pragma unroll
            for (int mt = 0; mt < 2; mt++) {
                int fb = f0w + mt * 16;
                int k = kk + ((g >> 1) << 3) + i;
                int cf = (fb >> 3) + (g & 1);
                u32 addr = as_base + (u32)((k * 128 + ((cf ^ (k & 7)) << 3)) * 2);
                asm volatile("ldmatrix.sync.aligned.m8n8.x4.trans.shared.b16 {%0,%1,%2,%3}, [%4];"
                    : "=r"(a[mt][0]), "=r"(a[mt][1]), "=r"(a[mt][2]), "=r"(a[mt][3]) : "r"(addr));
            }
            u32 b[8][2];
            #pragma unroll
            for (int np = 0; np < 4; np++) {
                int nb = j0w + np * 16;
                int k = kk + ((g & 1) << 3) + i;
                int cf = (nb >> 3) + (g >> 1);
                u32 addr = bs_base + (u32)((k * 128 + ((cf ^ (k & 7)) << 3)) * 2);
                asm volatile("ldmatrix.sync.aligned.m8n8.x4.trans.shared.b16 {%0,%1,%2,%3}, [%4];"
                    : "=r"(b[np * 2][0]), "=r"(b[np * 2][1]), "=r"(b[np * 2 + 1][0]), "=r"(b[np * 2 + 1][1])
                    : "r"(addr));
            }
            #pragma unroll
            for (int mt = 0; mt < 2; mt++)
                #pragma unroll
                for (int nt = 0; nt < 8; nt++)
                    asm volatile("mma.sync.aligned.m16n8k16.row.col.f32.f16.f16.f32 "
                        "{%0,%1,%2,%3}, {%4,%5,%6,%7}, {%8,%9}, {%0,%1,%2,%3};"
                        : "+f"(c[mt][nt][0]), "+f"(c[mt][nt][1]), "+f"(c[mt][nt][2]), "+f"(c[mt][nt][3])
                        : "r"(a[mt][0]), "r"(a[mt][1]), "r"(a[mt][2]), "r"(a[mt][3]),
                          "r"(b[nt][0]), "r"(b[nt][1]));
        }
    }

    float* P = g_part + ((size_t)ks * M_MATS + m) * F * 128;
    int fr = lane >> 2, jc = (lane & 3) * 2;
    #pragma unroll
    for (int mt = 0; mt < 2; mt++)
        #pragma unroll
        for (int nt = 0; nt < 8; nt++) {
            int f = f0w + mt * 16 + fr;
            int j = j0w + nt * 8 + jc;
            *(float2*)(P + (size_t)f * 128 + j) = make_float2(c[mt][nt][0], c[mt][nt][1]);
            *(float2*)(P + (size_t)(f + 8) * 128 + j) = make_float2(c[mt][nt][2], c[mt][nt][3]);
        }
}

// ---------------- reduce partials + bias + GRU epilogue ----------------
__global__ void finish(const float* __restrict__ hx, const float* __restrict__ b_ru,
                       const float* __restrict__ b_c, float* __restrict__ out) {
    int idx = blockIdx.x * blockDim.x + threadIdx.x;  // over 7*128*64
    if (idx >= M_MATS * F * U_DIM) return;
    int j = idx & 63;
    int f = (idx >> 6) & 127;
    int m = idx >> 13;
    float su = __ldg(b_ru + 64 + j);
    float sc = __ldg(b_c + j);
    const float* P = g_part + (size_t)m * F * 128 + (size_t)f * 128;
    #pragma unroll 3
    for (int ks = 0; ks < KSPLIT; ks++) {
        const float* Pk = P + (size_t)ks * M_MATS * F * 128;
        su += Pk[j];
        sc += Pk[64 + j];
    }
    float u = 1.f / (1.f + expf(-su));
    int r = f * M_MATS + m;
    float h = __ldg(hx + r * U_DIM + j);
    out[r * U_DIM + j] = u * h + (1.f - u) * tanhf(sc);
}

// ---------------- launcher ----------------
extern "C" void kernel_launch(void* const* d_in, const int* in_sizes, int n_in,
                              void* d_out, int out_size) {
    const float* inputs   = (const float*)d_in[0];
    const float* hx       = (const float*)d_in[1];
    const float* w_ru     = (const float*)d_in[2];
    const float* b_ru     = (const float*)d_in[3];
    const float* w_c      = (const float*)d_in[4];
    const float* b_c      = (const float*)d_in[5];
    const float* lap_vals = (const float*)d_in[6];
    const float* rw_vals  = (const float*)d_in[7];
    const int*   lrows    = (const int*)d_in[8];
    const int*   lcols    = (const int*)d_in[9];
    const int*   rrows    = (const int*)d_in[10];
    const int*   rcols    = (const int*)d_in[11];
    float* out = (float*)d_out;

    const int TB = 256;
    const int gE4 = (NNZ / 4 + TB - 1) / TB;
    const int gSp = N_NODES / 16;  // 3125 exact

    // CSR build (4 launches)
    zero2<<<(N_NODES + TB - 1) / TB, TB>>>();
    hist2<<<dim3(gE4, 2), TB>>>(lrows, rrows);
    scan2<<<2, 1024>>>();
    scatter2<<<dim3(gE4, 2), TB>>>(lrows, lcols, lap_vals, rrows, rcols, rw_vals);

    // x0 transpose + weight conversion (1 launch)
    prep<<<(N_NODES * 192 + TB - 1) / TB, TB>>>(inputs, w_ru, w_c);

    // SpMM chain (4 phases):
    // xs1 = L x0; {xs2 = 2 L xs1 - x0, xs3 = R xs1}; t = R xs3 (xs5=t, xs4=2t-xs1); xs6 = 2 R xs5 - xs3
    spmm_w<<<gSp, 256>>>(0, 0, 1, 0, 0, 0);          // launch #6 — ncu target
    spmm_dual<<<dim3(gSp, 2), 256>>>();
    spmm_w<<<gSp, 256>>>(1, 3, 4, 1, 5, 2);
    spmm_w<<<gSp, 256>>>(1, 5, 6, 3, 0, 1);

    // tensor-core GEMM + fused epilogue
    gemm_h<<<dim3(KSPLIT, M_MATS), 256>>>();
    finish<<<(M_MATS * F * U_DIM + TB - 1) / TB, TB>>>(hx, b_ru, b_c, out);
}